// round 17
// baseline (speedup 1.0000x reference)
#include <cuda_runtime.h>
#include <cstdint>

// Problem constants (B=256, T=2048, D=128)
#define BB 256
#define TT 2048
#define DD 128
#define MM (BB * TT)

typedef unsigned long long ull;

// Scratch: [m][3][128] fp32 : j=0 -> E, j=1 -> L=sigmoid, j=2 -> W=sigmoid
__device__ float g_elw[(size_t)MM * 384];

// ---------------------------------------------------------------------------
// helpers
// ---------------------------------------------------------------------------
__device__ __forceinline__ ull ffma2(ull a, ull b, ull c) {
    ull d;
    asm("fma.rn.f32x2 %0, %1, %2, %3;" : "=l"(d) : "l"(a), "l"(b), "l"(c));
    return d;
}

__device__ __forceinline__ float2 u2f2(ull v) {
    float2 r;
    asm("mov.b64 {%0,%1}, %2;" : "=f"(r.x), "=f"(r.y) : "l"(v));
    return r;
}

__device__ __forceinline__ float tanh_approx(float x) {
    float y;
    asm("tanh.approx.f32 %0, %1;" : "=f"(y) : "f"(x));
    return y;
}

// pack two f32 into f16x2: element0 = lo, element1 = hi
__device__ __forceinline__ uint32_t h2(float lo, float hi) {
    uint32_t d;
    asm("cvt.rn.f16x2.f32 %0, %1, %2;" : "=r"(d) : "f"(hi), "f"(lo));
    return d;
}

// ---------------------------------------------------------------------------
// Kernel 1: fused 3-way projection GEMM, fp16 mma m16n8k16, fp32 accumulate.
// M_TILE=64, 8 warps = 4 m-tiles x 2 n-halves. 3 full-K stages (one per W).
// B staged in smem in mma fragment-lane order -> coalesced LDS.64, 0 conflicts.
// A fragments hoisted to registers once (conflict-free LDS.32 from padded Xs).
// smem: Xs[64][68] u32 (17408B) + Bfrag[16][8][32] ull (32768B) = 50176B
//   -> 2 CTAs/SM.
// ---------------------------------------------------------------------------
#define PJ_SMEM 50176

__global__ __launch_bounds__(256) void proj_kernel(
    const float* __restrict__ X,
    const float* __restrict__ We, const float* __restrict__ be,
    const float* __restrict__ Wl, const float* __restrict__ bl,
    const float* __restrict__ Ww, const float* __restrict__ bw)
{
    extern __shared__ __align__(16) unsigned char smraw[];
    uint32_t* Xs    = (uint32_t*)smraw;            // [64][68] f16x2 pairs
    ull*      Bfrag = (ull*)(smraw + 64 * 68 * 4); // [ntile][ks][lane]

    const int tid  = threadIdx.x;
    const int warp = tid >> 5;
    const int lane = tid & 31;
    const int g    = lane >> 2;          // 0..7
    const int c    = lane & 3;           // 0..3
    const int mt   = warp & 3;           // m-tile (16 rows)
    const int nh   = warp >> 2;          // n-half (64 cols)
    const long m0  = (long)blockIdx.x * 64;
    const int r0   = mt * 16 + g;

    // ---- load X tile -> packed f16x2 in Xs ----
    const float4* X4 = (const float4*)(X + m0 * DD);
    #pragma unroll
    for (int i = 0; i < 8; i++) {
        int idx = tid + i * 256;         // 0..2047 float4
        int row = idx >> 5;
        int c4  = idx & 31;
        float4 v = X4[idx];
        Xs[row * 68 + 2 * c4]     = h2(v.x, v.y);
        Xs[row * 68 + 2 * c4 + 1] = h2(v.z, v.w);
    }
    __syncthreads();

    // ---- A fragments for full K (8 k-steps x 4 regs), conflict-free ----
    uint32_t A[8][4];
    #pragma unroll
    for (int kt = 0; kt < 8; kt++) {
        int base = 8 * kt + c;
        A[kt][0] = Xs[r0 * 68 + base];
        A[kt][1] = Xs[(r0 + 8) * 68 + base];
        A[kt][2] = Xs[r0 * 68 + base + 4];
        A[kt][3] = Xs[(r0 + 8) * 68 + base + 4];
    }

    float acc[8][4];

    #pragma unroll 1
    for (int s = 0; s < 3; s++) {
        const float* Wj = (s == 0) ? We : ((s == 1) ? Wl : Ww);
        const float* bj = (s == 0) ? be : ((s == 1) ? bl : bw);

        #pragma unroll
        for (int nt = 0; nt < 8; nt++)
            #pragma unroll
            for (int q = 0; q < 4; q++) acc[nt][q] = 0.0f;

        __syncthreads();   // previous stage's Bfrag consumers done

        // ---- stage Wj as fragment-ordered fp16 (4096 ull) ----
        #pragma unroll
        for (int i = 0; i < 16; i++) {
            int idx   = tid + i * 256;       // 0..4095
            int ntile = idx >> 8;
            int rem   = idx & 255;
            int ks    = rem >> 5;
            int ln    = rem & 31;
            int gg    = ln >> 2, cc = ln & 3;
            const float* wr = Wj + (ntile * 8 + gg) * 128 + ks * 16 + 2 * cc;
            uint32_t lo = h2(wr[0], wr[1]);
            uint32_t hi = h2(wr[8], wr[9]);
            Bfrag[idx] = (ull)lo | ((ull)hi << 32);
        }
        __syncthreads();

        // ---- mma loop: 8 kt x 8 nt per warp ----
        #pragma unroll
        for (int kt = 0; kt < 8; kt++) {
            #pragma unroll
            for (int nt = 0; nt < 8; nt++) {
                const int ntile = nh * 8 + nt;
                ull bbv = Bfrag[ntile * 256 + kt * 32 + lane];
                uint32_t b0 = (uint32_t)bbv, b1 = (uint32_t)(bbv >> 32);
                asm volatile(
                    "mma.sync.aligned.m16n8k16.row.col.f32.f16.f16.f32 "
                    "{%0,%1,%2,%3}, {%4,%5,%6,%7}, {%8,%9}, {%0,%1,%2,%3};\n"
                    : "+f"(acc[nt][0]), "+f"(acc[nt][1]),
                      "+f"(acc[nt][2]), "+f"(acc[nt][3])
                    : "r"(A[kt][0]), "r"(A[kt][1]),
                      "r"(A[kt][2]), "r"(A[kt][3]),
                      "r"(b0), "r"(b1));
            }
        }

        // ---- epilogue: bias (+ sigmoid for s>0), interleaved store ----
        long row0 = m0 + mt * 16 + g;
        #pragma unroll
        for (int nt = 0; nt < 8; nt++) {
            int col = nh * 64 + nt * 8 + 2 * c;
            float2 bbi = *(const float2*)&bj[col];
            float v0 = acc[nt][0] + bbi.x;
            float v1 = acc[nt][1] + bbi.y;
            float v2 = acc[nt][2] + bbi.x;
            float v3 = acc[nt][3] + bbi.y;
            if (s > 0) {
                v0 = 1.0f / (1.0f + __expf(-v0));
                v1 = 1.0f / (1.0f + __expf(-v1));
                v2 = 1.0f / (1.0f + __expf(-v2));
                v3 = 1.0f / (1.0f + __expf(-v3));
            }
            *(float2*)&g_elw[(row0 * 3 + s) * 128 + col]       = make_float2(v0, v1);
            *(float2*)&g_elw[((row0 + 8) * 3 + s) * 128 + col] = make_float2(v2, v3);
        }
    }
}

// ---------------------------------------------------------------------------
// Kernel 2: recurrence with split-K through smem partials.
// 128 CTAs x 256 threads; warp w: row r = w>>2, k-slice s = w&3.
// FMA phase: warp reads ONLY its 32-float belief slice (broadcast), computes
//   partial dots for outputs {l, l+32, l+64, l+96} (64 FFMA2, chains 16).
// bar(row) -> combine phase: same warp sums 4 partials for outputs
//   [32s,32s+32), gates (depth-2 LDG prefetch), tanh.approx, writes belief.
// bar(row). Two named barriers per row per step; rows fully decoupled.
// ---------------------------------------------------------------------------
__global__ __launch_bounds__(256, 1) void recur_kernel(
    const float* __restrict__ Wp, const float* __restrict__ bp,
    float* __restrict__ out)
{
    __shared__ __align__(16) float bel[2][2][128];   // [buf][row][k]
    __shared__ __align__(16) float part[2][4][128];  // [row][slice][e]

    const int tid = threadIdx.x;
    const int w   = tid >> 5;
    const int l   = tid & 31;
    const int r   = w >> 2;          // row
    const int s   = w & 3;           // k-slice
    const int ec  = 32 * s + l;      // combine-phase output index
    const long b  = (long)blockIdx.x * 2 + r;

    // weights: output e_j = l + 32j, k in [32s, 32s+32) -> 16 ull each
    ull wp[4][16];
    #pragma unroll
    for (int j = 0; j < 4; j++) {
        const ull* src = (const ull*)(Wp + (l + 32 * j) * 128 + 32 * s);
        #pragma unroll
        for (int i = 0; i < 16; i++) wp[j][i] = src[i];
    }
    const float biasc = bp[ec];

    bel[0][tid >> 7][tid & 127] = 0.0f;
    __syncthreads();

    const float* ep = g_elw + ((long)b * TT) * 384 + ec;
    float* outp = out + b * (long)TT * 128 + ec;

    float ev0 = ep[0],   lv0 = ep[128],       wv0 = ep[256];
    float ev1 = ep[384], lv1 = ep[384 + 128], wv1 = ep[384 + 256];
    float belr = 0.0f;

#define RSTEP(T, CUR, EV, LV, WV) do {                                         \
    const ulonglong2* bq = (const ulonglong2*)&bel[CUR][r][32 * s];            \
    ull a0 = 0ull, a1 = 0ull, a2 = 0ull, a3 = 0ull;                            \
    _Pragma("unroll")                                                          \
    for (int i = 0; i < 8; i++) {                                              \
        ulonglong2 bv = bq[i];                                                 \
        a0 = ffma2(wp[0][2*i], bv.x, a0); a0 = ffma2(wp[0][2*i+1], bv.y, a0);  \
        a1 = ffma2(wp[1][2*i], bv.x, a1); a1 = ffma2(wp[1][2*i+1], bv.y, a1);  \
        a2 = ffma2(wp[2][2*i], bv.x, a2); a2 = ffma2(wp[2][2*i+1], bv.y, a2);  \
        a3 = ffma2(wp[3][2*i], bv.x, a3); a3 = ffma2(wp[3][2*i+1], bv.y, a3);  \
    }                                                                          \
    float2 p0 = u2f2(a0), p1 = u2f2(a1), p2 = u2f2(a2), p3 = u2f2(a3);         \
    part[r][s][l]      = p0.x + p0.y;                                          \
    part[r][s][l + 32] = p1.x + p1.y;                                          \
    part[r][s][l + 64] = p2.x + p2.y;                                          \
    part[r][s][l + 96] = p3.x + p3.y;                                          \
    asm volatile("bar.sync %0, 128;\n" :: "r"(r + 1) : "memory");              \
    float sum = (part[r][0][ec] + part[r][1][ec]) +                            \
                (part[r][2][ec] + part[r][3][ec]);                             \
    float pre  = sum + biasc + (EV);                                           \
    float cand = tanh_approx(pre);                                             \
    float nb   = (LV) * belr + (WV) * cand;                                    \
    belr = nb;                                                                 \
    outp[(long)(T) * 128] = nb;                                                \
    bel[(CUR) ^ 1][r][ec] = nb;                                                \
    if ((T) + 2 < TT) {                                                        \
        const float* pp = ep + (long)((T) + 2) * 384;                          \
        EV = pp[0]; LV = pp[128]; WV = pp[256];                                \
    }                                                                          \
    asm volatile("bar.sync %0, 128;\n" :: "r"(r + 1) : "memory");              \
} while (0)

    for (int t = 0; t < TT; t += 2) {
        RSTEP(t,     0, ev0, lv0, wv0);
        RSTEP(t + 1, 1, ev1, lv1, wv1);
    }
#undef RSTEP
}

// ---------------------------------------------------------------------------
// launch
// ---------------------------------------------------------------------------
extern "C" void kernel_launch(void* const* d_in, const int* in_sizes, int n_in,
                              void* d_out, int out_size) {
    const float* X  = (const float*)d_in[0];
    const float* We = (const float*)d_in[1];
    const float* be = (const float*)d_in[2];
    const float* Wp = (const float*)d_in[3];
    const float* bp = (const float*)d_in[4];
    const float* Wl = (const float*)d_in[5];
    const float* bl = (const float*)d_in[6];
    const float* Ww = (const float*)d_in[7];
    const float* bw = (const float*)d_in[8];
    float* out = (float*)d_out;

    cudaFuncSetAttribute(proj_kernel,
                         cudaFuncAttributeMaxDynamicSharedMemorySize, PJ_SMEM);

    proj_kernel<<<MM / 64, 256, PJ_SMEM>>>(X, We, be, Wl, bl, Ww, bw);
    recur_kernel<<<BB / 2, 256>>>(Wp, bp, out);
}